// round 1
// baseline (speedup 1.0000x reference)
#include <cuda_runtime.h>
#include <math.h>

#define Ldim 2048
#define Sdim 2048
#define Nb   2
#define Ed   512
#define Hh   8
#define Dd   64

#define WOFF ((size_t)Ldim * Nb * Ed)   // offset of attn_weights in d_out

// Scratch in head-major layout: [n][h][seq][d]
__device__ float g_Q[(size_t)Nb * Hh * Ldim * Dd];
__device__ float g_K[(size_t)Nb * Hh * Sdim * Dd];
__device__ float g_V[(size_t)Nb * Hh * Sdim * Dd];
__device__ float g_O[(size_t)Nb * Hh * Ldim * Dd];

// ---------------------------------------------------------------------------
// Projection: C[m,j] = sum_k X[m,k] * W[j,k] + b[j], m=(t,n) row of [T*N, E].
// Output scattered to out[n][h][t][d] with j = h*64+d.
// Tiles 64x64, kt=32, 256 threads, 4x4 micro-tile.
// ---------------------------------------------------------------------------
__global__ void proj_kernel(const float* __restrict__ X,
                            const float* __restrict__ W,
                            const float* __restrict__ bias,
                            float* __restrict__ out)
{
    __shared__ float As[64][33];
    __shared__ float Bs[64][33];
    const int m0 = blockIdx.y * 64;
    const int j0 = blockIdx.x * 64;
    const int tid = threadIdx.x;
    const int tx = tid & 15, ty = tid >> 4;

    float acc[4][4] = {};

    for (int kt = 0; kt < Ed; kt += 32) {
        #pragma unroll
        for (int i = 0; i < 2; ++i) {
            int idx = tid + i * 256;          // 0..511 (float4 index)
            int row = idx >> 3;               // 0..63
            int c4  = idx & 7;                // 0..7
            float4 va = *(const float4*)(X + (size_t)(m0 + row) * Ed + kt + c4 * 4);
            As[row][c4*4+0] = va.x; As[row][c4*4+1] = va.y;
            As[row][c4*4+2] = va.z; As[row][c4*4+3] = va.w;
            float4 vb = *(const float4*)(W + (size_t)(j0 + row) * Ed + kt + c4 * 4);
            Bs[row][c4*4+0] = vb.x; Bs[row][c4*4+1] = vb.y;
            Bs[row][c4*4+2] = vb.z; Bs[row][c4*4+3] = vb.w;
        }
        __syncthreads();
        #pragma unroll 8
        for (int k = 0; k < 32; ++k) {
            float a0 = As[ty*4+0][k], a1 = As[ty*4+1][k];
            float a2 = As[ty*4+2][k], a3 = As[ty*4+3][k];
            float b0 = Bs[tx*4+0][k], b1 = Bs[tx*4+1][k];
            float b2 = Bs[tx*4+2][k], b3 = Bs[tx*4+3][k];
            acc[0][0] = fmaf(a0,b0,acc[0][0]); acc[0][1] = fmaf(a0,b1,acc[0][1]);
            acc[0][2] = fmaf(a0,b2,acc[0][2]); acc[0][3] = fmaf(a0,b3,acc[0][3]);
            acc[1][0] = fmaf(a1,b0,acc[1][0]); acc[1][1] = fmaf(a1,b1,acc[1][1]);
            acc[1][2] = fmaf(a1,b2,acc[1][2]); acc[1][3] = fmaf(a1,b3,acc[1][3]);
            acc[2][0] = fmaf(a2,b0,acc[2][0]); acc[2][1] = fmaf(a2,b1,acc[2][1]);
            acc[2][2] = fmaf(a2,b2,acc[2][2]); acc[2][3] = fmaf(a2,b3,acc[2][3]);
            acc[3][0] = fmaf(a3,b0,acc[3][0]); acc[3][1] = fmaf(a3,b1,acc[3][1]);
            acc[3][2] = fmaf(a3,b2,acc[3][2]); acc[3][3] = fmaf(a3,b3,acc[3][3]);
        }
        __syncthreads();
    }

    #pragma unroll
    for (int i = 0; i < 4; ++i) {
        int m = m0 + ty * 4 + i;
        int t = m >> 1;           // N == 2
        int n = m & 1;
        #pragma unroll
        for (int jj = 0; jj < 4; ++jj) {
            int j = j0 + tx * 4 + jj;
            int h = j >> 6, d = j & 63;
            out[(((size_t)n * Hh + h) * Ldim + t) * Dd + d] = acc[i][jj] + bias[j];
        }
    }
}

// ---------------------------------------------------------------------------
// Scores: per z=(h*N+n): W[z,l,s] = (Q_hn[l,:] . K_hn[s,:]) / 8 + attn_bias[l,s]
// Full K-dim (64) in one pass. Tiles 64x64.
// ---------------------------------------------------------------------------
__global__ void qk_kernel(const float* __restrict__ attn_bias,
                          float* __restrict__ wout)
{
    __shared__ float Qs[64][65];
    __shared__ float Ks[64][65];
    const int s0 = blockIdx.x * 64;
    const int l0 = blockIdx.y * 64;
    const int z  = blockIdx.z;            // h*Nb + n
    const int h = z / Nb, n = z % Nb;
    const float* Qb = g_Q + ((size_t)n * Hh + h) * Ldim * Dd;
    const float* Kb = g_K + ((size_t)n * Hh + h) * Sdim * Dd;
    const int tid = threadIdx.x;
    const int tx = tid & 15, ty = tid >> 4;

    #pragma unroll
    for (int i = 0; i < 4; ++i) {
        int idx = tid + i * 256;          // 0..1023 (float4 index)
        int row = idx >> 4;               // 0..63
        int c4  = idx & 15;               // 0..15
        float4 va = *(const float4*)(Qb + (size_t)(l0 + row) * Dd + c4 * 4);
        Qs[row][c4*4+0] = va.x; Qs[row][c4*4+1] = va.y;
        Qs[row][c4*4+2] = va.z; Qs[row][c4*4+3] = va.w;
        float4 vb = *(const float4*)(Kb + (size_t)(s0 + row) * Dd + c4 * 4);
        Ks[row][c4*4+0] = vb.x; Ks[row][c4*4+1] = vb.y;
        Ks[row][c4*4+2] = vb.z; Ks[row][c4*4+3] = vb.w;
    }
    __syncthreads();

    float acc[4][4] = {};
    #pragma unroll 16
    for (int k = 0; k < 64; ++k) {
        float a0 = Qs[ty*4+0][k], a1 = Qs[ty*4+1][k];
        float a2 = Qs[ty*4+2][k], a3 = Qs[ty*4+3][k];
        float b0 = Ks[tx*4+0][k], b1 = Ks[tx*4+1][k];
        float b2 = Ks[tx*4+2][k], b3 = Ks[tx*4+3][k];
        acc[0][0] = fmaf(a0,b0,acc[0][0]); acc[0][1] = fmaf(a0,b1,acc[0][1]);
        acc[0][2] = fmaf(a0,b2,acc[0][2]); acc[0][3] = fmaf(a0,b3,acc[0][3]);
        acc[1][0] = fmaf(a1,b0,acc[1][0]); acc[1][1] = fmaf(a1,b1,acc[1][1]);
        acc[1][2] = fmaf(a1,b2,acc[1][2]); acc[1][3] = fmaf(a1,b3,acc[1][3]);
        acc[2][0] = fmaf(a2,b0,acc[2][0]); acc[2][1] = fmaf(a2,b1,acc[2][1]);
        acc[2][2] = fmaf(a2,b2,acc[2][2]); acc[2][3] = fmaf(a2,b3,acc[2][3]);
        acc[3][0] = fmaf(a3,b0,acc[3][0]); acc[3][1] = fmaf(a3,b1,acc[3][1]);
        acc[3][2] = fmaf(a3,b2,acc[3][2]); acc[3][3] = fmaf(a3,b3,acc[3][3]);
    }

    #pragma unroll
    for (int i = 0; i < 4; ++i) {
        int l = l0 + ty * 4 + i;
        float4 bi = *(const float4*)(attn_bias + (size_t)l * Sdim + s0 + tx * 4);
        float4 r;
        r.x = fmaf(acc[i][0], 0.125f, bi.x);
        r.y = fmaf(acc[i][1], 0.125f, bi.y);
        r.z = fmaf(acc[i][2], 0.125f, bi.z);
        r.w = fmaf(acc[i][3], 0.125f, bi.w);
        *(float4*)(wout + ((size_t)z * Ldim + l) * Sdim + s0 + tx * 4) = r;
    }
}

// ---------------------------------------------------------------------------
// In-place softmax over last dim (S=2048). One 256-thread block per row.
// ---------------------------------------------------------------------------
__global__ void softmax_kernel(float* __restrict__ wout)
{
    float* p = wout + (size_t)blockIdx.x * Sdim;
    const int tid = threadIdx.x;
    __shared__ float red[8];

    float x[8];
    float m = -1e30f;
    #pragma unroll
    for (int i = 0; i < 8; ++i) { x[i] = p[tid + i * 256]; m = fmaxf(m, x[i]); }

    #pragma unroll
    for (int o = 16; o; o >>= 1) m = fmaxf(m, __shfl_xor_sync(0xffffffffu, m, o));
    if ((tid & 31) == 0) red[tid >> 5] = m;
    __syncthreads();
    float mb = red[0];
    #pragma unroll
    for (int w = 1; w < 8; ++w) mb = fmaxf(mb, red[w]);
    __syncthreads();

    float s = 0.f;
    #pragma unroll
    for (int i = 0; i < 8; ++i) { x[i] = __expf(x[i] - mb); s += x[i]; }

    #pragma unroll
    for (int o = 16; o; o >>= 1) s += __shfl_xor_sync(0xffffffffu, s, o);
    if ((tid & 31) == 0) red[tid >> 5] = s;
    __syncthreads();
    float sb = 0.f;
    #pragma unroll
    for (int w = 0; w < 8; ++w) sb += red[w];

    float inv = 1.0f / sb;
    #pragma unroll
    for (int i = 0; i < 8; ++i) p[tid + i * 256] = x[i] * inv;
}

// ---------------------------------------------------------------------------
// PV: per z=(h*N+n): O_hn[l,d] = sum_s P[z,l,s] * V_hn[s,d]. Tiles 64x64, kt=32.
// ---------------------------------------------------------------------------
__global__ void pv_kernel(const float* __restrict__ wts)
{
    __shared__ float Ps[64][33];
    __shared__ float Vs[32][65];
    const int l0 = blockIdx.x * 64;
    const int z  = blockIdx.y;
    const int h = z / Nb, n = z % Nb;
    const float* Pb = wts + (size_t)z * Ldim * Sdim;
    const float* Vb = g_V + ((size_t)n * Hh + h) * Sdim * Dd;
    const int tid = threadIdx.x;
    const int tx = tid & 15, ty = tid >> 4;

    float acc[4][4] = {};

    for (int s0 = 0; s0 < Sdim; s0 += 32) {
        #pragma unroll
        for (int i = 0; i < 2; ++i) {
            int idx = tid + i * 256;       // 0..511 (float4 index)
            // P tile: 64 rows x 32 cols
            int row = idx >> 3;
            int c4  = idx & 7;
            float4 v = *(const float4*)(Pb + (size_t)(l0 + row) * Sdim + s0 + c4 * 4);
            Ps[row][c4*4+0] = v.x; Ps[row][c4*4+1] = v.y;
            Ps[row][c4*4+2] = v.z; Ps[row][c4*4+3] = v.w;
            // V tile: 32 rows x 64 cols
            int kk = idx >> 4;
            int cv = idx & 15;
            float4 w = *(const float4*)(Vb + (size_t)(s0 + kk) * Dd + cv * 4);
            Vs[kk][cv*4+0] = w.x; Vs[kk][cv*4+1] = w.y;
            Vs[kk][cv*4+2] = w.z; Vs[kk][cv*4+3] = w.w;
        }
        __syncthreads();
        #pragma unroll 8
        for (int k = 0; k < 32; ++k) {
            float a0 = Ps[ty*4+0][k], a1 = Ps[ty*4+1][k];
            float a2 = Ps[ty*4+2][k], a3 = Ps[ty*4+3][k];
            float b0 = Vs[k][tx*4+0], b1 = Vs[k][tx*4+1];
            float b2 = Vs[k][tx*4+2], b3 = Vs[k][tx*4+3];
            acc[0][0] = fmaf(a0,b0,acc[0][0]); acc[0][1] = fmaf(a0,b1,acc[0][1]);
            acc[0][2] = fmaf(a0,b2,acc[0][2]); acc[0][3] = fmaf(a0,b3,acc[0][3]);
            acc[1][0] = fmaf(a1,b0,acc[1][0]); acc[1][1] = fmaf(a1,b1,acc[1][1]);
            acc[1][2] = fmaf(a1,b2,acc[1][2]); acc[1][3] = fmaf(a1,b3,acc[1][3]);
            acc[2][0] = fmaf(a2,b0,acc[2][0]); acc[2][1] = fmaf(a2,b1,acc[2][1]);
            acc[2][2] = fmaf(a2,b2,acc[2][2]); acc[2][3] = fmaf(a2,b3,acc[2][3]);
            acc[3][0] = fmaf(a3,b0,acc[3][0]); acc[3][1] = fmaf(a3,b1,acc[3][1]);
            acc[3][2] = fmaf(a3,b2,acc[3][2]); acc[3][3] = fmaf(a3,b3,acc[3][3]);
        }
        __syncthreads();
    }

    #pragma unroll
    for (int i = 0; i < 4; ++i) {
        int l = l0 + ty * 4 + i;
        float4 r; r.x = acc[i][0]; r.y = acc[i][1]; r.z = acc[i][2]; r.w = acc[i][3];
        *(float4*)(g_O + (((size_t)n * Hh + h) * Ldim + l) * Dd + tx * 4) = r;
    }
}

// ---------------------------------------------------------------------------
// Output projection: out[m=(l,n), j] = sum_e A[m,e] * Wo[j,e] + bo[j],
// where A[m, e=h*64+d] gathered from g_O[n][h][l][d].
// ---------------------------------------------------------------------------
__global__ void oproj_kernel(const float* __restrict__ Wo,
                             const float* __restrict__ bo,
                             float* __restrict__ out)
{
    __shared__ float As[64][33];
    __shared__ float Bs[64][33];
    const int m0 = blockIdx.y * 64;   // m = l*Nb + n
    const int j0 = blockIdx.x * 64;
    const int tid = threadIdx.x;
    const int tx = tid & 15, ty = tid >> 4;

    float acc[4][4] = {};

    for (int kt = 0; kt < Ed; kt += 32) {
        const int hsel = kt >> 6;
        const int dsel = kt & 63;
        #pragma unroll
        for (int i = 0; i < 2; ++i) {
            int idx = tid + i * 256;
            int row = idx >> 3;
            int c4  = idx & 7;
            int m = m0 + row;
            int l = m >> 1, nn = m & 1;
            float4 va = *(const float4*)(g_O +
                (((size_t)nn * Hh + hsel) * Ldim + l) * Dd + dsel + c4 * 4);
            As[row][c4*4+0] = va.x; As[row][c4*4+1] = va.y;
            As[row][c4*4+2] = va.z; As[row][c4*4+3] = va.w;
            float4 vb = *(const float4*)(Wo + (size_t)(j0 + row) * Ed + kt + c4 * 4);
            Bs[row][c4*4+0] = vb.x; Bs[row][c4*4+1] = vb.y;
            Bs[row][c4*4+2] = vb.z; Bs[row][c4*4+3] = vb.w;
        }
        __syncthreads();
        #pragma unroll 8
        for (int k = 0; k < 32; ++k) {
            float a0 = As[ty*4+0][k], a1 = As[ty*4+1][k];
            float a2 = As[ty*4+2][k], a3 = As[ty*4+3][k];
            float b0 = Bs[tx*4+0][k], b1 = Bs[tx*4+1][k];
            float b2 = Bs[tx*4+2][k], b3 = Bs[tx*4+3][k];
            acc[0][0] = fmaf(a0,b0,acc[0][0]); acc[0][1] = fmaf(a0,b1,acc[0][1]);
            acc[0][2] = fmaf(a0,b2,acc[0][2]); acc[0][3] = fmaf(a0,b3,acc[0][3]);
            acc[1][0] = fmaf(a1,b0,acc[1][0]); acc[1][1] = fmaf(a1,b1,acc[1][1]);
            acc[1][2] = fmaf(a1,b2,acc[1][2]); acc[1][3] = fmaf(a1,b3,acc[1][3]);
            acc[2][0] = fmaf(a2,b0,acc[2][0]); acc[2][1] = fmaf(a2,b1,acc[2][1]);
            acc[2][2] = fmaf(a2,b2,acc[2][2]); acc[2][3] = fmaf(a2,b3,acc[2][3]);
            acc[3][0] = fmaf(a3,b0,acc[3][0]); acc[3][1] = fmaf(a3,b1,acc[3][1]);
            acc[3][2] = fmaf(a3,b2,acc[3][2]); acc[3][3] = fmaf(a3,b3,acc[3][3]);
        }
        __syncthreads();
    }

    #pragma unroll
    for (int i = 0; i < 4; ++i) {
        int m = m0 + ty * 4 + i;
        float4 b4 = *(const float4*)(bo + j0 + tx * 4);
        float4 r;
        r.x = acc[i][0] + b4.x; r.y = acc[i][1] + b4.y;
        r.z = acc[i][2] + b4.z; r.w = acc[i][3] + b4.w;
        *(float4*)(out + (size_t)m * Ed + j0 + tx * 4) = r;
    }
}

// ---------------------------------------------------------------------------
extern "C" void kernel_launch(void* const* d_in, const int* in_sizes, int n_in,
                              void* d_out, int out_size)
{
    const float* query     = (const float*)d_in[0];
    const float* key       = (const float*)d_in[1];
    const float* value     = (const float*)d_in[2];
    const float* attn_bias = (const float*)d_in[3];
    const float* Wq = (const float*)d_in[4];
    const float* bq = (const float*)d_in[5];
    const float* Wk = (const float*)d_in[6];
    const float* bk = (const float*)d_in[7];
    const float* Wv = (const float*)d_in[8];
    const float* bv = (const float*)d_in[9];
    const float* Wo = (const float*)d_in[10];
    const float* bo = (const float*)d_in[11];

    float* out = (float*)d_out;
    float* wts = out + WOFF;

    void *pQ, *pK, *pV;
    cudaGetSymbolAddress(&pQ, g_Q);
    cudaGetSymbolAddress(&pK, g_K);
    cudaGetSymbolAddress(&pV, g_V);

    dim3 blk(256);
    dim3 gproj(Ed / 64, (Ldim * Nb) / 64);            // (8, 64)
    proj_kernel<<<gproj, blk>>>(query, Wq, bq, (float*)pQ);
    proj_kernel<<<gproj, blk>>>(key,   Wk, bk, (float*)pK);
    proj_kernel<<<gproj, blk>>>(value, Wv, bv, (float*)pV);

    dim3 gqk(Sdim / 64, Ldim / 64, Hh * Nb);          // (32, 32, 16)
    qk_kernel<<<gqk, blk>>>(attn_bias, wts);

    softmax_kernel<<<dim3(Hh * Nb * Ldim), blk>>>(wts);   // 32768 rows

    dim3 gpv(Ldim / 64, Hh * Nb);                     // (32, 16)
    pv_kernel<<<gpv, blk>>>(wts);

    oproj_kernel<<<gproj, blk>>>(Wo, bo, out);
}